// round 2
// baseline (speedup 1.0000x reference)
#include <cuda_runtime.h>
#include <math.h>
#include <float.h>

#define BG    128
#define NPG0  512
#define ETOT  524288
#define NTMAX 65536
#define KK1   256
#define KK2   128
#define KK3   64

// ---------------- scratch (device globals: no allocations allowed) ----------
__device__ float g_t[(size_t)NTMAX * 128];     // x @ W
__device__ float g_h[(size_t)NTMAX * 128];     // gcn output (post-relu)
__device__ float g_x1[(size_t)BG * KK1 * 128]; // stage1 pooled features
__device__ float g_x2[(size_t)BG * KK2 * 128];
__device__ float g_x3[(size_t)BG * KK3 * 128];
__device__ float g_deg[NTMAX];
__device__ float g_dinv[NTMAX];
__device__ float g_score[NTMAX];
__device__ float g_sagg[NTMAX];
__device__ int   g_newidx[NTMAX];
__device__ int   g_src[ETOT];
__device__ int   g_dst[ETOT];
__device__ float g_emask[ETOT];
__device__ int   g_perm[BG * KK1];
__device__ float g_tanhv[BG * KK1];

// ---------------- helpers ---------------------------------------------------

__device__ __forceinline__ unsigned f2tf32(float x) {
    unsigned r;
    asm("cvt.rna.tf32.f32 %0, %1;" : "=r"(r) : "f"(x));
    return r;
}

__device__ __forceinline__ void mma_tf32(float* d, const unsigned* a, unsigned b0, unsigned b1) {
    asm volatile(
        "mma.sync.aligned.m16n8k8.row.col.f32.tf32.tf32.f32 "
        "{%0,%1,%2,%3},{%4,%5,%6,%7},{%8,%9},{%0,%1,%2,%3};"
        : "+f"(d[0]), "+f"(d[1]), "+f"(d[2]), "+f"(d[3])
        : "r"(a[0]), "r"(a[1]), "r"(a[2]), "r"(a[3]), "r"(b0), "r"(b1));
}

// ---------------- kernels ---------------------------------------------------

__global__ void k_fill_deg(int NT) {
    int i = blockIdx.x * blockDim.x + threadIdx.x;
    if (i < NT) g_deg[i] = 1.0f;   // self-loop
}

__global__ void k_deg(const int* __restrict__ dst, const float* __restrict__ emask) {
    int e = blockIdx.x * blockDim.x + threadIdx.x;
    if (e >= ETOT) return;
    float m = emask ? emask[e] : 1.0f;
    if (m != 0.0f) atomicAdd(&g_deg[dst[e]], m);
}

__global__ void k_dinv(int NT) {
    int i = blockIdx.x * blockDim.x + threadIdx.x;
    if (i < NT) g_dinv[i] = rsqrtf(g_deg[i]);
}

// t[NT,128] = X[NT,128] @ W[128,128] via 3xTF32 tensor-core MMA.
// Also fuses the GCN self-loop term: h = dinv^2 * t + b.
// CTA: 128 rows x 128 cols, 8 warps (4m x 2n), warp = 32 rows x 64 cols.
// smem: Wpair [128][132] float2 (hi,lo) + Xs [128][132] float.
#define GEMM_SMEM ((128 * 132 * 2 + 128 * 132) * 4)

__global__ __launch_bounds__(256, 1)
void k_gemm(const float* __restrict__ X, const float* __restrict__ W,
            const float* __restrict__ bvec, int NT) {
    extern __shared__ float sm[];
    float2* Wp = (float2*)sm;              // [128][132] (hi,lo) tf32 pairs
    float*  Xs = sm + 128 * 132 * 2;       // [128][132] fp32 tile
    const int tid = threadIdx.x;

    // stage W split into tf32 hi/lo
    for (int i = tid; i < 128 * 128; i += 256) {
        int k = i >> 7, n = i & 127;
        float w = W[i];
        unsigned hb = f2tf32(w);
        float hf = __uint_as_float(hb);
        unsigned lb = f2tf32(w - hf);
        Wp[k * 132 + n] = make_float2(hf, __uint_as_float(lb));
    }
    // stage X tile (coalesced float4)
    const int R0 = blockIdx.x * 128;
    const float4* Xg = (const float4*)(X + (size_t)R0 * 128);
    for (int i = tid; i < 128 * 32; i += 256) {
        int row = i >> 5, c = i & 31;
        float4 v = Xg[row * 32 + c];
        *(float4*)&Xs[row * 132 + c * 4] = v;
    }
    __syncthreads();

    const int lane = tid & 31, warp = tid >> 5;
    const int gID = lane >> 2, tg = lane & 3;
    const int mwarp = warp >> 1, nwarp = warp & 1;
    const int rbase = mwarp * 32;
    const int nbase = nwarp * 64;

    float acc[2][8][4];
#pragma unroll
    for (int mt = 0; mt < 2; mt++)
#pragma unroll
        for (int j = 0; j < 8; j++)
#pragma unroll
            for (int r = 0; r < 4; r++) acc[mt][j][r] = 0.0f;

#pragma unroll
    for (int ks = 0; ks < 16; ks++) {
        const int kb = ks * 8;
        unsigned ah[2][4], al[2][4];
#pragma unroll
        for (int mt = 0; mt < 2; mt++) {
            int rb = rbase + mt * 16;
            float x0 = Xs[(rb + gID) * 132 + kb + tg];
            float x1 = Xs[(rb + 8 + gID) * 132 + kb + tg];
            float x2 = Xs[(rb + gID) * 132 + kb + 4 + tg];
            float x3 = Xs[(rb + 8 + gID) * 132 + kb + 4 + tg];
            ah[mt][0] = f2tf32(x0); al[mt][0] = f2tf32(x0 - __uint_as_float(ah[mt][0]));
            ah[mt][1] = f2tf32(x1); al[mt][1] = f2tf32(x1 - __uint_as_float(ah[mt][1]));
            ah[mt][2] = f2tf32(x2); al[mt][2] = f2tf32(x2 - __uint_as_float(ah[mt][2]));
            ah[mt][3] = f2tf32(x3); al[mt][3] = f2tf32(x3 - __uint_as_float(ah[mt][3]));
        }
#pragma unroll
        for (int j = 0; j < 8; j++) {
            int n0 = nbase + j * 8;
            float2 p0 = Wp[(kb + tg) * 132 + n0 + gID];
            float2 p1 = Wp[(kb + 4 + tg) * 132 + n0 + gID];
            unsigned b0h = __float_as_uint(p0.x), b0l = __float_as_uint(p0.y);
            unsigned b1h = __float_as_uint(p1.x), b1l = __float_as_uint(p1.y);
#pragma unroll
            for (int mt = 0; mt < 2; mt++) {
                mma_tf32(acc[mt][j], ah[mt], b0h, b1h);
                mma_tf32(acc[mt][j], ah[mt], b0l, b1l);
                mma_tf32(acc[mt][j], al[mt], b0h, b1h);
            }
        }
    }
    __syncthreads();

    // stage accumulators back into Xs for coalesced writeback
#pragma unroll
    for (int mt = 0; mt < 2; mt++)
#pragma unroll
        for (int j = 0; j < 8; j++)
#pragma unroll
            for (int r = 0; r < 4; r++) {
                int row = rbase + mt * 16 + gID + ((r >> 1) ? 8 : 0);
                int col = nbase + j * 8 + tg * 2 + (r & 1);
                Xs[row * 132 + col] = acc[mt][j][r];
            }
    __syncthreads();

    // fused writeback: t and h = dinv^2 * t + b
    for (int i = tid; i < 128 * 32; i += 256) {
        int row = i >> 5, c4 = (i & 31) * 4;
        float4 v = *(float4*)&Xs[row * 132 + c4];
        int gr = R0 + row;
        float di = g_dinv[gr];
        float s = di * di;
        float4 b = *(const float4*)&bvec[c4];
        *(float4*)&g_t[(size_t)gr * 128 + c4] = v;
        float4 h = make_float4(v.x * s + b.x, v.y * s + b.y, v.z * s + b.z, v.w * s + b.w);
        *(float4*)&g_h[(size_t)gr * 128 + c4] = h;
    }
}

// h[dst] += dinv[src]*dinv[dst]*m * t[src]   (one warp per edge, v4 red atomics)
__global__ void k_edge_agg(const int* __restrict__ src, const int* __restrict__ dst,
                           const float* __restrict__ emask) {
    int w = (blockIdx.x * blockDim.x + threadIdx.x) >> 5;
    int lane = threadIdx.x & 31;
    if (w >= ETOT) return;
    float m = emask ? emask[w] : 1.0f;
    if (m == 0.0f) return;
    int s = src[w], d = dst[w];
    float norm = g_dinv[s] * g_dinv[d] * m;
    float4 t = *(const float4*)&g_t[(size_t)s * 128 + lane * 4];
    float* p = &g_h[(size_t)d * 128 + lane * 4];
    asm volatile("red.global.add.v4.f32 [%0], {%1,%2,%3,%4};"
                 :: "l"(p), "f"(t.x * norm), "f"(t.y * norm), "f"(t.z * norm), "f"(t.w * norm)
                 : "memory");
}

// fused: relu(h) in place + score = h @ Ws + sagg init (self term).  warp/node
__global__ void k_post(const float* __restrict__ Wsv, const float* __restrict__ bsv, int NT) {
    int w = (blockIdx.x * blockDim.x + threadIdx.x) >> 5;
    int lane = threadIdx.x & 31;
    if (w >= NT) return;
    float4* hp = (float4*)&g_h[(size_t)w * 128 + lane * 4];
    float4 h4 = *hp;
    h4.x = fmaxf(h4.x, 0.f); h4.y = fmaxf(h4.y, 0.f);
    h4.z = fmaxf(h4.z, 0.f); h4.w = fmaxf(h4.w, 0.f);
    *hp = h4;
    float4 w4 = *(const float4*)&Wsv[lane * 4];
    float v = h4.x * w4.x + h4.y * w4.y + h4.z * w4.z + h4.w * w4.w;
#pragma unroll
    for (int o = 16; o; o >>= 1) v += __shfl_xor_sync(0xffffffffu, v, o);
    if (lane == 0) {
        g_score[w] = v;
        float di = g_dinv[w];
        g_sagg[w] = di * di * v + bsv[0];
    }
}

__global__ void k_sagg_edge(const int* __restrict__ src, const int* __restrict__ dst,
                            const float* __restrict__ emask) {
    int e = blockIdx.x * blockDim.x + threadIdx.x;
    if (e >= ETOT) return;
    float m = emask ? emask[e] : 1.0f;
    if (m == 0.0f) return;
    int s = src[e], d = dst[e];
    atomicAdd(&g_sagg[d], g_dinv[s] * g_dinv[d] * m * g_score[s]);
}

// per-graph top-k via bitonic sort of (negated score, idx); one block per graph
__global__ void k_topk(int n_pg, int kk) {
    __shared__ float vals[512];
    __shared__ int   idxs[512];
    int g = blockIdx.x, i = threadIdx.x;   // blockDim == n_pg (power of 2)
    int base = g * n_pg;
    vals[i] = -g_sagg[base + i];
    idxs[i] = i;
    g_newidx[base + i] = -1;
    __syncthreads();
    for (int k2 = 2; k2 <= n_pg; k2 <<= 1) {
        for (int j = k2 >> 1; j > 0; j >>= 1) {
            int ixj = i ^ j;
            if (ixj > i) {
                bool up = ((i & k2) == 0);
                float vi = vals[i], vj = vals[ixj];
                bool sw = up ? (vi > vj) : (vi < vj);
                if (sw) {
                    vals[i] = vj; vals[ixj] = vi;
                    int t = idxs[i]; idxs[i] = idxs[ixj]; idxs[ixj] = t;
                }
            }
            __syncthreads();
        }
    }
    if (i < kk) {
        int node = base + idxs[i];
        int nid = g * kk + i;
        g_newidx[node] = nid;
        g_perm[nid] = node;
        g_tanhv[nid] = tanhf(-vals[i]);
    }
}

// fused gather (xnew = tanh(score)*h[perm]) + [max|mean] readout into out
__global__ void k_pool(float* __restrict__ xout, int kk, float* __restrict__ out, int accFlag) {
    int g = blockIdx.x, c = threadIdx.x;  // 128 threads
    float mx = -FLT_MAX, sm = 0.f;
    for (int j = 0; j < kk; j++) {
        int row = g * kk + j;
        float v = g_h[(size_t)g_perm[row] * 128 + c] * g_tanhv[row];
        xout[(size_t)row * 128 + c] = v;
        mx = fmaxf(mx, v);
        sm += v;
    }
    float mean = sm / (float)kk;
    if (accFlag) {
        out[g * 256 + c]       += mx;
        out[g * 256 + 128 + c] += mean;
    } else {
        out[g * 256 + c]       = mx;
        out[g * 256 + 128 + c] = mean;
    }
}

__global__ void k_remap(const int* __restrict__ src_in, const int* __restrict__ dst_in,
                        const float* __restrict__ emask_in) {
    int e = blockIdx.x * blockDim.x + threadIdx.x;
    if (e >= ETOT) return;
    float m = emask_in ? emask_in[e] : 1.0f;
    int s = src_in[e], d = dst_in[e];
    int ns = g_newidx[s], nd = g_newidx[d];
    bool valid = (ns >= 0) && (nd >= 0);
    g_src[e] = valid ? ns : 0;
    g_dst[e] = valid ? nd : 0;
    g_emask[e] = (valid && m != 0.0f) ? 1.0f : 0.0f;
}

// ---------------- host driver ----------------------------------------------

static void run_stage(const float* xin, int n_pg, int kk,
                      const float* W, const float* bvec, const float* Wsv, const float* bsv,
                      const int* src, const int* dst, const float* emask,
                      float* xout, float* out, int accFlag, int doRemap) {
    int NT = BG * n_pg;
    k_fill_deg<<<NT / 256, 256>>>(NT);
    k_deg<<<ETOT / 256, 256>>>(dst, emask);
    k_dinv<<<NT / 256, 256>>>(NT);
    k_gemm<<<NT / 128, 256, GEMM_SMEM>>>(xin, W, bvec, NT);
    k_edge_agg<<<ETOT / 8, 256>>>(src, dst, emask);
    k_post<<<NT / 8, 256>>>(Wsv, bsv, NT);
    k_sagg_edge<<<ETOT / 256, 256>>>(src, dst, emask);
    k_topk<<<BG, n_pg>>>(n_pg, kk);
    k_pool<<<BG, 128>>>(xout, kk, out, accFlag);
    if (doRemap) k_remap<<<ETOT / 256, 256>>>(src, dst, emask);
}

extern "C" void kernel_launch(void* const* d_in, const int* in_sizes, int n_in,
                              void* d_out, int out_size) {
    (void)in_sizes; (void)n_in; (void)out_size;
    const float* x   = (const float*)d_in[0];
    const int*   ei  = (const int*)d_in[1];
    const float* W1  = (const float*)d_in[3];
    const float* b1  = (const float*)d_in[4];
    const float* Ws1 = (const float*)d_in[5];
    const float* bs1 = (const float*)d_in[6];
    const float* W2  = (const float*)d_in[7];
    const float* b2  = (const float*)d_in[8];
    const float* Ws2 = (const float*)d_in[9];
    const float* bs2 = (const float*)d_in[10];
    const float* W3  = (const float*)d_in[11];
    const float* b3  = (const float*)d_in[12];
    const float* Ws3 = (const float*)d_in[13];
    const float* bs3 = (const float*)d_in[14];
    float* out = (float*)d_out;

    static int smem_set = 0;
    if (!smem_set) {
        cudaFuncSetAttribute(k_gemm, cudaFuncAttributeMaxDynamicSharedMemorySize, GEMM_SMEM);
        smem_set = 1;
    }

    float *px1, *px2, *px3;
    int *psrc, *pdst;
    float *pmask;
    cudaGetSymbolAddress((void**)&px1, g_x1);
    cudaGetSymbolAddress((void**)&px2, g_x2);
    cudaGetSymbolAddress((void**)&px3, g_x3);
    cudaGetSymbolAddress((void**)&psrc, g_src);
    cudaGetSymbolAddress((void**)&pdst, g_dst);
    cudaGetSymbolAddress((void**)&pmask, g_emask);

    const int* src0 = ei;
    const int* dst0 = ei + ETOT;

    // Stage 1: N=512 -> K1=256
    run_stage(x, NPG0, KK1, W1, b1, Ws1, bs1, src0, dst0, nullptr, px1, out, 0, 1);
    // Stage 2: K1=256 -> K2=128
    run_stage(px1, KK1, KK2, W2, b2, Ws2, bs2, psrc, pdst, pmask, px2, out, 1, 1);
    // Stage 3: K2=128 -> K3=64
    run_stage(px2, KK2, KK3, W3, b3, Ws3, bs3, psrc, pdst, pmask, px3, out, 1, 0);
}